// round 13
// baseline (speedup 1.0000x reference)
#include <cuda_runtime.h>

typedef unsigned long long ull;

#define B_   256
#define T_   1000
#define H_   512
#define NTN  16          // column tiles (32 cols each)
#define NTM  8           // batch tiles (32 batches each)
#define NCTA (NTN*NTM)   // 128
#define NTHR 512
#define KC   128         // K chunk staged in smem
#define NCH  (H_/KC)     // 4
#define HSS  132         // padded row stride (floats)
#define RS   520         // reduction array stride (128*4 + 8 pad)

// shared memory layout (float offsets)
#define OFF_W4Z 0
#define OFF_W4R 16384
#define OFF_W4H 32768
#define OFF_HS  49152
#define HS_BUF  (32*HSS)                 // 4224 floats per buffer
#define OFF_C   (OFF_HS + 2*HS_BUF)      // 57600 (red aliases both buffers: 16*520=8320 <= 8448)
#define SMEM_FLOATS (OFF_C + 256)        // 57856
#define SMEM_BYTES  (SMEM_FLOATS*4)      // 231424

// persistent device state
__device__ float g_hstate[B_*H_];        // compact h_t (L2-hot)
__device__ float g_hr[B_*H_];
__device__ float g_k[B_];
__device__ float g_kpart[NTN*B_];
__device__ unsigned g_cnt[NTM*32];

// ---- packed f32x2 helpers (Blackwell FFMA2 via PTX) ----
__device__ __forceinline__ ull fma2(ull a, ull b, ull c){ ull d; asm("fma.rn.f32x2 %0,%1,%2,%3;":"=l"(d):"l"(a),"l"(b),"l"(c)); return d; }
__device__ __forceinline__ void unpack2(ull v, float& lo, float& hi){ asm("mov.b64 {%0,%1},%2;":"=f"(lo),"=f"(hi):"l"(v)); }
__device__ __forceinline__ float hsum2(ull v){ float lo,hi; unpack2(v,lo,hi); return lo+hi; }

__device__ __forceinline__ float sigm(float x){ return 1.0f/(1.0f+__expf(-x)); }
__device__ __forceinline__ float tanh_(float x){ return 2.0f/(1.0f+__expf(-2.0f*x)) - 1.0f; }

// ---- cp.async helpers (.cg = L2-coherent, bypass L1) ----
__device__ __forceinline__ void cpasync16(float* dst_smem, const float* src){
    unsigned d = (unsigned)__cvta_generic_to_shared(dst_smem);
    asm volatile("cp.async.cg.shared.global [%0], [%1], 16;" :: "r"(d), "l"(src) : "memory");
}
#define CP_COMMIT() asm volatile("cp.async.commit_group;" ::: "memory")
#define CP_WAIT0()  asm volatile("cp.async.wait_group 0;" ::: "memory")

// split group barrier on a monotonic counter (16 CTAs per group)
__device__ __forceinline__ void bar_arrive(unsigned* cnt){
    __syncthreads();
    if (threadIdx.x == 0){
        asm volatile("red.release.gpu.global.add.u32 [%0], 1;" :: "l"(cnt) : "memory");
    }
}
__device__ __forceinline__ void bar_wait(unsigned* cnt, unsigned target){
    if (threadIdx.x == 0){
        unsigned v;
        do { asm volatile("ld.acquire.gpu.global.u32 %0, [%1];" : "=r"(v) : "l"(cnt) : "memory"); } while (v < target);
    }
    __syncthreads();
}

__global__ void init_kernel(){
    int i = threadIdx.x;
    if (i < NTM*32) g_cnt[i] = 0u;
}

// MAC blocks: hreg = ulonglong2, .x = h pair (k0,k1), .y = (k2,k3)
#define P1B(hreg, wz0, wz1, wr0, wr1, AZ, AR) \
    AZ.x = fma2(hreg.x, wz0.x, AZ.x); AZ.y = fma2(hreg.x, wz0.y, AZ.y); \
    AR.x = fma2(hreg.x, wr0.x, AR.x); AR.y = fma2(hreg.x, wr0.y, AR.y); \
    AZ.x = fma2(hreg.y, wz1.x, AZ.x); AZ.y = fma2(hreg.y, wz1.y, AZ.y); \
    AR.x = fma2(hreg.y, wr1.x, AR.x); AR.y = fma2(hreg.y, wr1.y, AR.y);

#define P2B(hreg, w0, w1, AH) \
    AH.x = fma2(hreg.x, w0.x, AH.x); AH.y = fma2(hreg.x, w0.y, AH.y); \
    AH.x = fma2(hreg.y, w1.x, AH.x); AH.y = fma2(hreg.y, w1.y, AH.y);

__global__ void __launch_bounds__(NTHR, 1) mcgru_kernel(
    const float* __restrict__ inp, const float* __restrict__ St, const float* __restrict__ Mass,
    const float* __restrict__ Wz, const float* __restrict__ bz,
    const float* __restrict__ Wr, const float* __restrict__ br,
    const float* __restrict__ Wh, const float* __restrict__ bh,
    const float* __restrict__ Wk, const float* __restrict__ bk,
    float* __restrict__ out)
{
    extern __shared__ float sm[];
    float* hS0 = sm + OFF_HS;
    float* hS1 = sm + OFF_HS + HS_BUF;
    float* red = sm + OFF_HS;            // alias over both buffers (used when MACs done)
    float* cs  = sm + OFF_C;             // epilogue constants
    const ulonglong2* W4Zu = (const ulonglong2*)(sm + OFF_W4Z);
    const ulonglong2* W4Ru = (const ulonglong2*)(sm + OFF_W4R);
    const ulonglong2* W4Hu = (const ulonglong2*)(sm + OFF_W4H);

    const int tid   = threadIdx.x;
    const int tileN = blockIdx.x & (NTN-1);
    const int tileM = blockIdx.x >> 4;
    const int c0    = tileN * 32;
    const int kh    = tid >> 7;          // k-quarter 0..3
    const int r7    = tid & 127;
    const int p     = r7 & 15;           // col pair -> cols c0+2p, c0+2p+1
    const int bq    = r7 >> 4;           // 0..7 -> accumulates batches 4bq..4bq+3
    const int b0    = bq * 4;
    const int gbase = tileM*32 + b0;
    const int jp    = 2*p;
    const int cc    = c0 + jp;
    unsigned* cnt   = &g_cnt[tileM*32];

    // epilogue ownership: this thread finalizes batch bE = b0 + kh, cols cc/cc+1
    const int bE  = b0 + kh;
    const int gbE = tileM*32 + bE;

    // ---- prologue: interleaved weight layout in SMEM ----
    // W4[kq][pp] = {w[2kq][c0+2pp], w[2kq+1][c0+2pp], w[2kq][c0+2pp+1], w[2kq+1][c0+2pp+1]}
    for (int i = tid; i < 4096; i += NTHR){
        int kq = i >> 4, pp = i & 15;
        int c = c0 + 2*pp;
        const float2 z0 = *(const float2*)&Wz[(2*kq+1)*H_ + c];
        const float2 z1 = *(const float2*)&Wz[(2*kq+2)*H_ + c];
        ((float4*)(sm + OFF_W4Z))[i] = make_float4(z0.x, z1.x, z0.y, z1.y);
        const float2 r0 = *(const float2*)&Wr[(2*kq+1)*H_ + c];
        const float2 r1 = *(const float2*)&Wr[(2*kq+2)*H_ + c];
        ((float4*)(sm + OFF_W4R))[i] = make_float4(r0.x, r1.x, r0.y, r1.y);
        const float2 h0 = *(const float2*)&Wh[(2*kq+1)*H_ + c];
        const float2 h1 = *(const float2*)&Wh[(2*kq+2)*H_ + c];
        ((float4*)(sm + OFF_W4H))[i] = make_float4(h0.x, h1.x, h0.y, h1.y);
    }
    if (tid < 32){
        cs[tid]       = Wz[c0 + tid];            // vz0
        cs[32 + tid]  = Wr[c0 + tid];            // vr0
        cs[64 + tid]  = Wh[c0 + tid];            // vh0
        cs[96 + tid]  = Wh[513*H_ + c0 + tid];   // v513
        cs[128 + tid] = Wh[514*H_ + c0 + tid];   // v514
        cs[160 + tid] = bz[c0 + tid];
        cs[192 + tid] = br[c0 + tid];
        cs[224 + tid] = bh[c0 + tid];
    }
    const float wkH = __ldg(&Wk[H_]);
    const float bk0 = __ldg(&bk[0]);
    const float2 wkf = *(const float2*)&Wk[cc];
    const float stE = __ldg(&St[gbE]);
    const float msE = __ldg(&Mass[gbE]);
    __syncthreads();

    // t-invariant staging addresses (2 float4 per thread per 128-k chunk)
    int sdst[2];
    const float* hsrc1[2];  // phase1 source: g_hstate
    const float* hsrc2[2];  // phase2 source: g_hr
    #pragma unroll
    for (int u = 0; u < 2; u++){
        int i = tid + u*NTHR;
        int row = i >> 5, c4 = (i & 31)*4;
        sdst[u]  = row*HSS + c4;
        hsrc1[u] = g_hstate + (tileM*32 + row)*H_ + c4;
        hsrc2[u] = g_hr     + (tileM*32 + row)*H_ + c4;
    }
    // running pointers for owned batch
    float* outE = out + (size_t)gbE*T_*H_ + cc;
    const float* inpE = inp + (size_t)gbE*T_;

    float2 hoE = make_float2(0.f, 0.f);   // own h_{t-1}(bE, cc..cc+1)
    float2 zE;

    float kreg = 0.0f;
    unsigned bar = 0;

    #pragma unroll 1
    for (int t = 0; t < T_; t++){
        // ---- k finalize from step t-1 partials (leader column-tile) ----
        if (tileN == 0 && tid < 32){
            int gb = tileM*32 + tid;
            if (t == 0){
                kreg = 0.0f;
            } else {
                float s = kreg * wkH + bk0;
                #pragma unroll
                for (int n = 0; n < NTN; n++) s += __ldcg(&g_kpart[n*B_ + gb]);
                kreg = sigm(s);
            }
            g_k[gb] = kreg;
        }

        const float xbE = __ldg(inpE + t);

        // ---- phase 1: z, r = sigmoid([x, h_{t-1}] @ W + b) ----
        float sz0, sz1, sr0, sr1;
        if (t > 0){
            ulonglong2 az[4], ar[4];
            #pragma unroll
            for (int i = 0; i < 4; i++){ az[i] = make_ulonglong2(0,0); ar[i] = make_ulonglong2(0,0); }

            #pragma unroll
            for (int u = 0; u < 2; u++) cpasync16(hS0 + sdst[u], hsrc1[u]);
            CP_COMMIT();
            #pragma unroll 1
            for (int ch = 0; ch < NCH; ch++){
                float* buf = (ch & 1) ? hS1 : hS0;
                CP_WAIT0();
                __syncthreads();           // chunk ch visible to all; MAC(ch-1) done by all
                if (ch < NCH-1){
                    float* nbuf = (ch & 1) ? hS0 : hS1;
                    int kc = (ch+1)*KC;
                    #pragma unroll
                    for (int u = 0; u < 2; u++) cpasync16(nbuf + sdst[u], hsrc1[u] + kc);
                    CP_COMMIT();
                }
                const ulonglong2* wz = W4Zu + (ch*64 + kh*16)*16 + p;
                const ulonglong2* wr = W4Ru + (ch*64 + kh*16)*16 + p;
                const float* hb = buf + kh*32;
                #pragma unroll 4
                for (int it = 0; it < 8; it++){
                    ulonglong2 wz0 = wz[(2*it)*16],   wr0 = wr[(2*it)*16];
                    ulonglong2 wz1 = wz[(2*it+1)*16], wr1 = wr[(2*it+1)*16];
                    ulonglong2 hh0 = *(const ulonglong2*)(hb + (b0+0)*HSS + 4*it);
                    ulonglong2 hh1 = *(const ulonglong2*)(hb + (b0+1)*HSS + 4*it);
                    ulonglong2 hh2 = *(const ulonglong2*)(hb + (b0+2)*HSS + 4*it);
                    ulonglong2 hh3 = *(const ulonglong2*)(hb + (b0+3)*HSS + 4*it);
                    P1B(hh0, wz0, wz1, wr0, wr1, az[0], ar[0])
                    P1B(hh1, wz0, wz1, wr0, wr1, az[1], ar[1])
                    P1B(hh2, wz0, wz1, wr0, wr1, az[2], ar[2])
                    P1B(hh3, wz0, wz1, wr0, wr1, az[3], ar[3])
                }
            }
            __syncthreads();   // all MACs done before red overwrites buffers
            {
                int wb = kh*128 + r7;
                #pragma unroll
                for (int i = 0; i < 4; i++){
                    red[(2*i+0)*RS + wb]   = hsum2(az[i].x);
                    red[(2*i+1)*RS + wb]   = hsum2(az[i].y);
                    red[(8+2*i+0)*RS + wb] = hsum2(ar[i].x);
                    red[(8+2*i+1)*RS + wb] = hsum2(ar[i].y);
                }
            }
            __syncthreads();
            // each thread gathers the 4 quarter-partials of ITS batch (i = kh)
            sz0 = sz1 = sr0 = sr1 = 0.f;
            #pragma unroll
            for (int q = 0; q < 4; q++){
                sz0 += red[(2*kh+0)*RS + q*128 + r7];
                sz1 += red[(2*kh+1)*RS + q*128 + r7];
                sr0 += red[(8+2*kh+0)*RS + q*128 + r7];
                sr1 += red[(8+2*kh+1)*RS + q*128 + r7];
            }
        } else {
            sz0 = sz1 = sr0 = sr1 = 0.f;
        }

        // per-thread epilogue for batch bE (all 16 warps busy)
        {
            const float2 vr0 = *(const float2*)(cs + 32 + jp);
            const float2 brf = *(const float2*)(cs + 192 + jp);
            float r0 = sigm(sr0 + xbE*vr0.x + brf.x);
            float r1 = sigm(sr1 + xbE*vr0.y + brf.y);
            *(float2*)&g_hr[gbE*H_ + cc] = make_float2(hoE.x*r0, hoE.y*r1);
        }

        bar++; bar_arrive(cnt);

        {
            const float2 vz0 = *(const float2*)(cs + jp);
            const float2 bzf = *(const float2*)(cs + 160 + jp);
            zE.x = sigm(sz0 + xbE*vz0.x + bzf.x);
            zE.y = sigm(sz1 + xbE*vz0.y + bzf.y);
        }

        bar_wait(cnt, bar*16);

        const float kvE = __ldcg(&g_k[gbE]);

        // ---- phase 2: h_tilde = tanh([x, h*r, St*k, Mass] @ Wh + bh) ----
        float sh0, sh1;
        {
            ulonglong2 ah[4];
            #pragma unroll
            for (int i = 0; i < 4; i++) ah[i] = make_ulonglong2(0,0);

            #pragma unroll
            for (int u = 0; u < 2; u++) cpasync16(hS0 + sdst[u], hsrc2[u]);
            CP_COMMIT();
            #pragma unroll 1
            for (int ch = 0; ch < NCH; ch++){
                float* buf = (ch & 1) ? hS1 : hS0;
                CP_WAIT0();
                __syncthreads();
                if (ch < NCH-1){
                    float* nbuf = (ch & 1) ? hS0 : hS1;
                    int kc = (ch+1)*KC;
                    #pragma unroll
                    for (int u = 0; u < 2; u++) cpasync16(nbuf + sdst[u], hsrc2[u] + kc);
                    CP_COMMIT();
                }
                const ulonglong2* wh = W4Hu + (ch*64 + kh*16)*16 + p;
                const float* hb = buf + kh*32;
                #pragma unroll 4
                for (int it = 0; it < 8; it++){
                    ulonglong2 w0 = wh[(2*it)*16], w1 = wh[(2*it+1)*16];
                    ulonglong2 hh0 = *(const ulonglong2*)(hb + (b0+0)*HSS + 4*it);
                    ulonglong2 hh1 = *(const ulonglong2*)(hb + (b0+1)*HSS + 4*it);
                    ulonglong2 hh2 = *(const ulonglong2*)(hb + (b0+2)*HSS + 4*it);
                    ulonglong2 hh3 = *(const ulonglong2*)(hb + (b0+3)*HSS + 4*it);
                    P2B(hh0, w0, w1, ah[0])
                    P2B(hh1, w0, w1, ah[1])
                    P2B(hh2, w0, w1, ah[2])
                    P2B(hh3, w0, w1, ah[3])
                }
            }
            __syncthreads();
            {
                int wb = kh*128 + r7;
                #pragma unroll
                for (int i = 0; i < 4; i++){
                    red[(2*i+0)*RS + wb] = hsum2(ah[i].x);
                    red[(2*i+1)*RS + wb] = hsum2(ah[i].y);
                }
            }
            __syncthreads();
            sh0 = sh1 = 0.f;
            #pragma unroll
            for (int q = 0; q < 4; q++){
                sh0 += red[(2*kh+0)*RS + q*128 + r7];
                sh1 += red[(2*kh+1)*RS + q*128 + r7];
            }
        }

        // per-thread epilogue for batch bE
        {
            const float2 vh0  = *(const float2*)(cs + 64 + jp);
            const float2 v513 = *(const float2*)(cs + 96 + jp);
            const float2 v514 = *(const float2*)(cs + 128 + jp);
            const float2 bhf  = *(const float2*)(cs + 224 + jp);
            float sk = stE * kvE;
            float a0 = sh0 + xbE*vh0.x + sk*v513.x + msE*v514.x + bhf.x;
            float a1 = sh1 + xbE*vh0.y + sk*v513.y + msE*v514.y + bhf.y;
            float t0 = tanh_(a0), t1 = tanh_(a1);
            float hn0 = (1.f - zE.x)*hoE.x + zE.x*t0;
            float hn1 = (1.f - zE.y)*hoE.y + zE.y*t1;
            float2 hn = make_float2(hn0, hn1);
            __stcs((float2*)outE, hn);                    // write-only stream
            outE += H_;
            *(float2*)&g_hstate[gbE*H_ + cc] = hn;        // L2-hot state
            hoE = hn;
            float kp = hn0*wkf.x + hn1*wkf.y;
            #pragma unroll
            for (int off = 8; off; off >>= 1)
                kp += __shfl_down_sync(0xffffffffu, kp, off, 16);
            if (p == 0)
                g_kpart[tileN*B_ + gbE] = kp;
        }

        bar++; bar_arrive(cnt);
        bar_wait(cnt, bar*16);
    }
}

extern "C" void kernel_launch(void* const* d_in, const int* in_sizes, int n_in,
                              void* d_out, int out_size) {
    (void)in_sizes; (void)n_in; (void)out_size;
    const float* inputs = (const float*)d_in[0];
    const float* St     = (const float*)d_in[1];
    const float* Mass   = (const float*)d_in[2];
    const float* Wz     = (const float*)d_in[3];
    const float* bz     = (const float*)d_in[4];
    const float* Wr     = (const float*)d_in[5];
    const float* br     = (const float*)d_in[6];
    const float* Wh     = (const float*)d_in[7];
    const float* bh     = (const float*)d_in[8];
    const float* Wk     = (const float*)d_in[9];
    const float* bk     = (const float*)d_in[10];
    float* out = (float*)d_out;

    cudaFuncSetAttribute(mcgru_kernel, cudaFuncAttributeMaxDynamicSharedMemorySize, SMEM_BYTES);

    init_kernel<<<1, 256>>>();
    mcgru_kernel<<<NCTA, NTHR, SMEM_BYTES>>>(inputs, St, Mass, Wz, bz, Wr, br,
                                             Wh, bh, Wk, bk, out);
}

// round 14
// speedup vs baseline: 1.8046x; 1.8046x over previous
#include <cuda_runtime.h>

#define B_   256
#define T_   1000
#define H_   512
#define NTN  16
#define NTM  8
#define NCTA 128
#define NTHR 512

// float offsets in dynamic smem
#define OFF_WZ  0
#define OFF_WR  16384
#define OFF_WH  32768
#define OFF_RED 49152            // 8448 floats; aliased by A staging (2 x 4224)
#define OFF_CS  57600            // 256 floats
#define SMEM_FLOATS 57856
#define SMEM_BYTES  (SMEM_FLOATS*4)   // 231424 B

#define ABUF  4224               // one staging buffer (hi+lo) in floats
#define AHALF 2112               // hi or lo half

// persistent device state
__device__ float g_hstate[B_*H_];
__device__ float g_hr[B_*H_];
__device__ float g_k[B_];
__device__ float g_kpart[NTN*B_];
__device__ unsigned g_cnt[NTM*32];

__device__ __forceinline__ unsigned cvt_tf32(float x){
    unsigned u; asm("cvt.rna.tf32.f32 %0, %1;" : "=r"(u) : "f"(x)); return u;
}
__device__ __forceinline__ void mma_tf32(float c[4], uint4 a, unsigned b0, unsigned b1){
    asm volatile("mma.sync.aligned.m16n8k8.row.col.f32.tf32.tf32.f32 "
                 "{%0,%1,%2,%3}, {%4,%5,%6,%7}, {%8,%9}, {%0,%1,%2,%3};"
                 : "+f"(c[0]), "+f"(c[1]), "+f"(c[2]), "+f"(c[3])
                 : "r"(a.x), "r"(a.y), "r"(a.z), "r"(a.w), "r"(b0), "r"(b1));
}
__device__ __forceinline__ float sigm(float x){ return 1.0f/(1.0f+__expf(-x)); }
__device__ __forceinline__ float tanh_(float x){ return 2.0f/(1.0f+__expf(-2.0f*x)) - 1.0f; }

__device__ __forceinline__ void group_barrier(unsigned* cnt, unsigned target){
    __syncthreads();
    if (threadIdx.x == 0){
        asm volatile("red.release.gpu.global.add.u32 [%0], 1;" :: "l"(cnt) : "memory");
        unsigned v;
        do { asm volatile("ld.acquire.gpu.global.u32 %0, [%1];" : "=r"(v) : "l"(cnt) : "memory"); } while (v < target);
    }
    __syncthreads();
}

__global__ void init_kernel(){
    int i = threadIdx.x;
    if (i < NTM*32) g_cnt[i] = 0u;
}

__global__ void __launch_bounds__(NTHR, 1) mcgru_kernel(
    const float* __restrict__ inp, const float* __restrict__ St, const float* __restrict__ Mass,
    const float* __restrict__ Wz, const float* __restrict__ bz,
    const float* __restrict__ Wr, const float* __restrict__ br,
    const float* __restrict__ Wh, const float* __restrict__ bh,
    const float* __restrict__ Wk, const float* __restrict__ bk,
    float* __restrict__ out)
{
    extern __shared__ float sm[];
    float* cs = sm + OFF_CS;

    const int tid   = threadIdx.x;
    const int lane  = tid & 31;
    const int wid   = tid >> 5;
    const int g     = lane >> 2;       // mma group id
    const int tig   = lane & 3;        // thread-in-group
    const int kq    = wid & 3;         // strided k-quarter
    const int ng    = wid >> 2;        // n-block (8 cols)
    const int cpair = 4*ng + tig;
    const int tileN = blockIdx.x & (NTN-1);
    const int tileM = blockIdx.x >> 4;
    const int c0    = tileN * 32;
    unsigned* cnt   = &g_cnt[tileM*32];

    // epilogue ownership: batch bE, cols cc..cc+1
    const int bE  = tid >> 4;
    const int cp  = tid & 15;
    const int jp2 = 2*cp;
    const int cc  = c0 + jp2;
    const int gbE = tileM*32 + bE;

    // ---- prologue: interleaved RAW fp32 weights (B-fragment order) ----
    // pair for (S, ng', lane'): { W[1+8S+tig'][c0+8ng'+g'], W[1+8S+tig'+4][c0+8ng'+g'] }
    for (int i = tid; i < 8192; i += NTHR){
        int S = i >> 7, rem = i & 127, ngg = rem >> 5, ln = rem & 31;
        int gg = ln >> 2, tg = ln & 3;
        int c = c0 + 8*ngg + gg;
        int r0 = 1 + 8*S + tg, r1 = r0 + 4;
        int dst = ((S*4 + ngg)*32 + ln)*2;
        sm[OFF_WZ + dst]   = Wz[r0*H_ + c];  sm[OFF_WZ + dst+1] = Wz[r1*H_ + c];
        sm[OFF_WR + dst]   = Wr[r0*H_ + c];  sm[OFF_WR + dst+1] = Wr[r1*H_ + c];
        sm[OFF_WH + dst]   = Wh[r0*H_ + c];  sm[OFF_WH + dst+1] = Wh[r1*H_ + c];
    }
    if (tid < 32){
        cs[tid]       = Wz[c0 + tid];
        cs[32 + tid]  = Wr[c0 + tid];
        cs[64 + tid]  = Wh[c0 + tid];
        cs[96 + tid]  = Wh[513*H_ + c0 + tid];
        cs[128 + tid] = Wh[514*H_ + c0 + tid];
        cs[160 + tid] = bz[c0 + tid];
        cs[192 + tid] = br[c0 + tid];
        cs[224 + tid] = bh[c0 + tid];
    }
    const float wkH = __ldg(&Wk[H_]);
    const float bk0 = __ldg(&bk[0]);
    const float2 wkf = *(const float2*)&Wk[cc];
    const float stE = __ldg(&St[gbE]);
    const float msE = __ldg(&Mass[gbE]);
    __syncthreads();

    // staging writer constants (thread-invariant): row rowW, 4 k-values at 4*qW
    const int rowW = tid >> 4;
    const int qW   = tid & 15;
    const int mtW  = rowW >> 4;
    const int rmW  = rowW & 15;
    const int sbase = ((mtW*8 + (qW>>1))*132) + (rmW & 7)*16 + ((rmW>>3) + 2*(qW&1));
    const float* src1 = g_hstate + (tileM*32 + rowW)*H_ + 4*qW;
    const float* src2 = g_hr     + (tileM*32 + rowW)*H_ + 4*qW;

    float* outE = out + (size_t)gbE*T_*H_ + cc;
    const float* inpE = inp + (size_t)gbE*T_;

    float2 hoE = make_float2(0.f, 0.f);
    float2 zE;
    float kreg = 0.0f;
    unsigned bar = 0;

    #pragma unroll 1
    for (int t = 0; t < T_; t++){
        // ---- k finalize from step t-1 partials (leader column-tile) ----
        if (tileN == 0 && tid < 32){
            int gb = tileM*32 + tid;
            if (t == 0){
                kreg = 0.0f;
            } else {
                float s = kreg * wkH + bk0;
                #pragma unroll
                for (int n = 0; n < NTN; n++) s += __ldcg(&g_kpart[n*B_ + gb]);
                kreg = sigm(s);
            }
            g_k[gb] = kreg;
        }

        const float xbE = __ldg(inpE + t);

        // ================= phase 1: z, r =================
        float2 sz = make_float2(0.f, 0.f), sr = make_float2(0.f, 0.f);
        if (t > 0){
            float cz[2][4] = {{0,0,0,0},{0,0,0,0}};
            float cr[2][4] = {{0,0,0,0},{0,0,0,0}};
            float4 pf = __ldcg((const float4*)src1);
            #pragma unroll 1
            for (int ch = 0; ch < 8; ch++){
                float* ab = sm + OFF_RED + (ch & 1)*ABUF;
                {   // stage hi/lo (tf32-split)
                    unsigned h0=cvt_tf32(pf.x), h1=cvt_tf32(pf.y), h2=cvt_tf32(pf.z), h3=cvt_tf32(pf.w);
                    float* dh = ab + sbase;
                    dh[0]=__uint_as_float(h0); dh[4]=__uint_as_float(h1);
                    dh[8]=__uint_as_float(h2); dh[12]=__uint_as_float(h3);
                    float* dl = dh + AHALF;
                    dl[0]=__uint_as_float(cvt_tf32(pf.x-__uint_as_float(h0)));
                    dl[4]=__uint_as_float(cvt_tf32(pf.y-__uint_as_float(h1)));
                    dl[8]=__uint_as_float(cvt_tf32(pf.z-__uint_as_float(h2)));
                    dl[12]=__uint_as_float(cvt_tf32(pf.w-__uint_as_float(h3)));
                }
                __syncthreads();
                if (ch < 7) pf = __ldcg((const float4*)(src1 + (ch+1)*64));
                #pragma unroll
                for (int j = 0; j < 2; j++){
                    const int sic = kq + 4*j;
                    const int sg  = ch*8 + sic;
                    float2 wz = *(const float2*)(sm + OFF_WZ + ((sg*4+ng)*32+lane)*2);
                    float2 wr = *(const float2*)(sm + OFF_WR + ((sg*4+ng)*32+lane)*2);
                    unsigned zh0=cvt_tf32(wz.x), zh1=cvt_tf32(wz.y);
                    unsigned zl0=cvt_tf32(wz.x-__uint_as_float(zh0));
                    unsigned zl1=cvt_tf32(wz.y-__uint_as_float(zh1));
                    unsigned rh0=cvt_tf32(wr.x), rh1=cvt_tf32(wr.y);
                    unsigned rl0=cvt_tf32(wr.x-__uint_as_float(rh0));
                    unsigned rl1=cvt_tf32(wr.y-__uint_as_float(rh1));
                    #pragma unroll
                    for (int mt = 0; mt < 2; mt++){
                        const float* ap = ab + (mt*8+sic)*132 + lane*4;
                        uint4 Ah = *(const uint4*)ap;
                        uint4 Al = *(const uint4*)(ap + AHALF);
                        mma_tf32(cz[mt], Ah, zh0, zh1);
                        mma_tf32(cz[mt], Ah, zl0, zl1);
                        mma_tf32(cz[mt], Al, zh0, zh1);
                        mma_tf32(cr[mt], Ah, rh0, rh1);
                        mma_tf32(cr[mt], Ah, rl0, rl1);
                        mma_tf32(cr[mt], Al, rh0, rh1);
                    }
                }
            }
            __syncthreads();   // staging region becomes reduction region
            #pragma unroll
            for (int mt = 0; mt < 2; mt++){
                int rw = mt*16 + g;
                *(float2*)(sm + OFF_RED + ((kq*16 + cpair)*33 + rw)*2)       = make_float2(cz[mt][0], cz[mt][1]);
                *(float2*)(sm + OFF_RED + ((kq*16 + cpair)*33 + rw + 8)*2)   = make_float2(cz[mt][2], cz[mt][3]);
                *(float2*)(sm + OFF_RED + (((4+kq)*16 + cpair)*33 + rw)*2)     = make_float2(cr[mt][0], cr[mt][1]);
                *(float2*)(sm + OFF_RED + (((4+kq)*16 + cpair)*33 + rw + 8)*2) = make_float2(cr[mt][2], cr[mt][3]);
            }
            __syncthreads();
            #pragma unroll
            for (int q = 0; q < 4; q++){
                float2 a = *(const float2*)(sm + OFF_RED + ((q*16 + cp)*33 + bE)*2);
                float2 b = *(const float2*)(sm + OFF_RED + (((4+q)*16 + cp)*33 + bE)*2);
                sz.x += a.x; sz.y += a.y; sr.x += b.x; sr.y += b.y;
            }
        }

        // per-thread epilogue: r first (data others need), then z
        {
            const float2 vr0 = *(const float2*)(cs + 32 + jp2);
            const float2 brf = *(const float2*)(cs + 192 + jp2);
            float r0 = sigm(sr.x + xbE*vr0.x + brf.x);
            float r1 = sigm(sr.y + xbE*vr0.y + brf.y);
            *(float2*)&g_hr[gbE*H_ + cc] = make_float2(hoE.x*r0, hoE.y*r1);
            const float2 vz0 = *(const float2*)(cs + jp2);
            const float2 bzf = *(const float2*)(cs + 160 + jp2);
            zE.x = sigm(sz.x + xbE*vz0.x + bzf.x);
            zE.y = sigm(sz.y + xbE*vz0.y + bzf.y);
        }

        bar++; group_barrier(cnt, bar*16);

        const float kvE = __ldcg(&g_k[gbE]);

        // ================= phase 2: h_tilde =================
        float2 sh = make_float2(0.f, 0.f);
        {
            float chh[2][4] = {{0,0,0,0},{0,0,0,0}};
            float4 pf = __ldcg((const float4*)src2);
            #pragma unroll 1
            for (int ch = 0; ch < 8; ch++){
                float* ab = sm + OFF_RED + (ch & 1)*ABUF;
                {
                    unsigned h0=cvt_tf32(pf.x), h1=cvt_tf32(pf.y), h2=cvt_tf32(pf.z), h3=cvt_tf32(pf.w);
                    float* dh = ab + sbase;
                    dh[0]=__uint_as_float(h0); dh[4]=__uint_as_float(h1);
                    dh[8]=__uint_as_float(h2); dh[12]=__uint_as_float(h3);
                    float* dl = dh + AHALF;
                    dl[0]=__uint_as_float(cvt_tf32(pf.x-__uint_as_float(h0)));
                    dl[4]=__uint_as_float(cvt_tf32(pf.y-__uint_as_float(h1)));
                    dl[8]=__uint_as_float(cvt_tf32(pf.z-__uint_as_float(h2)));
                    dl[12]=__uint_as_float(cvt_tf32(pf.w-__uint_as_float(h3)));
                }
                __syncthreads();
                if (ch < 7) pf = __ldcg((const float4*)(src2 + (ch+1)*64));
                #pragma unroll
                for (int j = 0; j < 2; j++){
                    const int sic = kq + 4*j;
                    const int sg  = ch*8 + sic;
                    float2 wh = *(const float2*)(sm + OFF_WH + ((sg*4+ng)*32+lane)*2);
                    unsigned hh0=cvt_tf32(wh.x), hh1=cvt_tf32(wh.y);
                    unsigned hl0=cvt_tf32(wh.x-__uint_as_float(hh0));
                    unsigned hl1=cvt_tf32(wh.y-__uint_as_float(hh1));
                    #pragma unroll
                    for (int mt = 0; mt < 2; mt++){
                        const float* ap = ab + (mt*8+sic)*132 + lane*4;
                        uint4 Ah = *(const uint4*)ap;
                        uint4 Al = *(const uint4*)(ap + AHALF);
                        mma_tf32(chh[mt], Ah, hh0, hh1);
                        mma_tf32(chh[mt], Ah, hl0, hl1);
                        mma_tf32(chh[mt], Al, hh0, hh1);
                    }
                }
            }
            __syncthreads();
            #pragma unroll
            for (int mt = 0; mt < 2; mt++){
                int rw = mt*16 + g;
                *(float2*)(sm + OFF_RED + ((kq*16 + cpair)*33 + rw)*2)     = make_float2(chh[mt][0], chh[mt][1]);
                *(float2*)(sm + OFF_RED + ((kq*16 + cpair)*33 + rw + 8)*2) = make_float2(chh[mt][2], chh[mt][3]);
            }
            __syncthreads();
            #pragma unroll
            for (int q = 0; q < 4; q++){
                float2 a = *(const float2*)(sm + OFF_RED + ((q*16 + cp)*33 + bE)*2);
                sh.x += a.x; sh.y += a.y;
            }
        }

        // final per-thread epilogue
        {
            const float2 vh0  = *(const float2*)(cs + 64 + jp2);
            const float2 v513 = *(const float2*)(cs + 96 + jp2);
            const float2 v514 = *(const float2*)(cs + 128 + jp2);
            const float2 bhf  = *(const float2*)(cs + 224 + jp2);
            float sk = stE * kvE;
            float a0 = sh.x + xbE*vh0.x + sk*v513.x + msE*v514.x + bhf.x;
            float a1 = sh.y + xbE*vh0.y + sk*v513.y + msE*v514.y + bhf.y;
            float t0 = tanh_(a0), t1 = tanh_(a1);
            float hn0 = (1.f - zE.x)*hoE.x + zE.x*t0;
            float hn1 = (1.f - zE.y)*hoE.y + zE.y*t1;
            float2 hn = make_float2(hn0, hn1);
            __stcs((float2*)outE, hn);
            outE += H_;
            *(float2*)&g_hstate[gbE*H_ + cc] = hn;
            hoE = hn;
            float kp = hn0*wkf.x + hn1*wkf.y;
            #pragma unroll
            for (int off = 8; off; off >>= 1)
                kp += __shfl_down_sync(0xffffffffu, kp, off, 16);
            if (cp == 0)
                g_kpart[tileN*B_ + gbE] = kp;
        }

        bar++; group_barrier(cnt, bar*16);
    }
}

extern "C" void kernel_launch(void* const* d_in, const int* in_sizes, int n_in,
                              void* d_out, int out_size) {
    (void)in_sizes; (void)n_in; (void)out_size;
    const float* inputs = (const float*)d_in[0];
    const float* St     = (const float*)d_in[1];
    const float* Mass   = (const float*)d_in[2];
    const float* Wz     = (const float*)d_in[3];
    const float* bz     = (const float*)d_in[4];
    const float* Wr     = (const float*)d_in[5];
    const float* br     = (const float*)d_in[6];
    const float* Wh     = (const float*)d_in[7];
    const float* bh     = (const float*)d_in[8];
    const float* Wk     = (const float*)d_in[9];
    const float* bk     = (const float*)d_in[10];
    float* out = (float*)d_out;

    cudaFuncSetAttribute(mcgru_kernel, cudaFuncAttributeMaxDynamicSharedMemorySize, SMEM_BYTES);

    init_kernel<<<1, 256>>>();
    mcgru_kernel<<<NCTA, NTHR, SMEM_BYTES>>>(inputs, St, Mass, Wz, bz, Wr, br,
                                             Wh, bh, Wk, bk, out);
}

// round 15
// speedup vs baseline: 1.8589x; 1.0301x over previous
#include <cuda_runtime.h>

#define B_   256
#define T_   1000
#define H_   512
#define NTN  16
#define NTM  8
#define NCTA 128
#define NTHR 512

// float offsets in dynamic smem
#define OFF_WZ  0
#define OFF_WR  16384
#define OFF_WH  32768
#define OFF_RED 49152            // 8448 floats: 2 staging buffers (hi+lo), aliased by reduction
#define OFF_CS  57600            // 256 floats
#define SMEM_FLOATS 57856
#define SMEM_BYTES  (SMEM_FLOATS*4)   // 231424 B

#define ABUF  4224               // one staging buffer (hi+lo) in floats
#define AHALF 2112               // hi or lo half

// persistent device state: h and h*r pre-split to tf32 hi/lo, stored in
// mma A-fragment order: idx(b,k) = ((B2*64+s)*32 + g*4+tig)*4 + (hi8+2*half)
//   B2 = (b>>5)*2 + ((b&31)>>4), g=(b&15)&7, hi8=(b&15)>>3, s=k>>3, tig=k&3, half=(k>>2)&1
__device__ float g_hA_hi[B_*H_];
__device__ float g_hA_lo[B_*H_];
__device__ float g_hrA_hi[B_*H_];
__device__ float g_hrA_lo[B_*H_];
__device__ float g_k[B_];
__device__ float g_kpart[NTN*B_];
__device__ unsigned g_cnt[NTM*32];

__device__ __forceinline__ unsigned cvt_tf32(float x){
    unsigned u; asm("cvt.rna.tf32.f32 %0, %1;" : "=r"(u) : "f"(x)); return u;
}
__device__ __forceinline__ float tf32f(float x){ return __uint_as_float(cvt_tf32(x)); }
__device__ __forceinline__ void mma_tf32(float c[4], uint4 a, unsigned b0, unsigned b1){
    asm volatile("mma.sync.aligned.m16n8k8.row.col.f32.tf32.tf32.f32 "
                 "{%0,%1,%2,%3}, {%4,%5,%6,%7}, {%8,%9}, {%0,%1,%2,%3};"
                 : "+f"(c[0]), "+f"(c[1]), "+f"(c[2]), "+f"(c[3])
                 : "r"(a.x), "r"(a.y), "r"(a.z), "r"(a.w), "r"(b0), "r"(b1));
}
__device__ __forceinline__ float sigm(float x){ return 1.0f/(1.0f+__expf(-x)); }
__device__ __forceinline__ float tanh_(float x){ return 2.0f/(1.0f+__expf(-2.0f*x)) - 1.0f; }

__device__ __forceinline__ void group_barrier(unsigned* cnt, unsigned target){
    __syncthreads();
    if (threadIdx.x == 0){
        asm volatile("red.release.gpu.global.add.u32 [%0], 1;" :: "l"(cnt) : "memory");
        unsigned v;
        do { asm volatile("ld.acquire.gpu.global.u32 %0, [%1];" : "=r"(v) : "l"(cnt) : "memory"); } while (v < target);
    }
    __syncthreads();
}

__global__ void init_kernel(){
    int i = threadIdx.x;
    if (i < NTM*32) g_cnt[i] = 0u;
}

__global__ void __launch_bounds__(NTHR, 1) mcgru_kernel(
    const float* __restrict__ inp, const float* __restrict__ St, const float* __restrict__ Mass,
    const float* __restrict__ Wz, const float* __restrict__ bz,
    const float* __restrict__ Wr, const float* __restrict__ br,
    const float* __restrict__ Wh, const float* __restrict__ bh,
    const float* __restrict__ Wk, const float* __restrict__ bk,
    float* __restrict__ out)
{
    extern __shared__ float sm[];
    float* cs = sm + OFF_CS;

    const int tid   = threadIdx.x;
    const int lane  = tid & 31;
    const int wid   = tid >> 5;
    const int g     = lane >> 2;       // mma group id
    const int tig   = lane & 3;        // thread-in-group
    const int kq    = wid & 3;         // strided k-quarter
    const int ng    = wid >> 2;        // n-block (8 cols)
    const int cpair = 4*ng + tig;
    const int tileN = blockIdx.x & (NTN-1);
    const int tileM = blockIdx.x >> 4;
    const int c0    = tileN * 32;
    unsigned* cnt   = &g_cnt[tileM*32];

    // epilogue ownership: batch bE, cols cc..cc+1
    const int bE  = tid >> 4;
    const int cp  = tid & 15;
    const int jp2 = 2*cp;
    const int cc  = c0 + jp2;
    const int gbE = tileM*32 + bE;

    // ---- prologue: interleaved RAW fp32 weights (B-fragment order) ----
    for (int i = tid; i < 8192; i += NTHR){
        int S = i >> 7, rem = i & 127, ngg = rem >> 5, ln = rem & 31;
        int gg = ln >> 2, tg = ln & 3;
        int c = c0 + 8*ngg + gg;
        int r0 = 1 + 8*S + tg, r1 = r0 + 4;
        int dst = ((S*4 + ngg)*32 + ln)*2;
        sm[OFF_WZ + dst]   = Wz[r0*H_ + c];  sm[OFF_WZ + dst+1] = Wz[r1*H_ + c];
        sm[OFF_WR + dst]   = Wr[r0*H_ + c];  sm[OFF_WR + dst+1] = Wr[r1*H_ + c];
        sm[OFF_WH + dst]   = Wh[r0*H_ + c];  sm[OFF_WH + dst+1] = Wh[r1*H_ + c];
    }
    if (tid < 32){
        cs[tid]       = Wz[c0 + tid];
        cs[32 + tid]  = Wr[c0 + tid];
        cs[64 + tid]  = Wh[c0 + tid];
        cs[96 + tid]  = Wh[513*H_ + c0 + tid];
        cs[128 + tid] = Wh[514*H_ + c0 + tid];
        cs[160 + tid] = bz[c0 + tid];
        cs[192 + tid] = br[c0 + tid];
        cs[224 + tid] = bh[c0 + tid];
    }
    const float wkH = __ldg(&Wk[H_]);
    const float bk0 = __ldg(&bk[0]);
    const float2 wkf = *(const float2*)&Wk[cc];
    const float stE = __ldg(&St[gbE]);
    const float msE = __ldg(&Mass[gbE]);
    __syncthreads();

    // ---- staging copy constants (t-invariant, pure copy: no cvt) ----
    // thread stages float4 #tid of each 64-k chunk: slice16 = mt*8+sic, laneS
    const int slice16 = tid >> 5;
    const int laneS   = tid & 31;
    const int B2s     = tileM*2 + (slice16 >> 3);
    const int base_f  = ((B2s*64 + (slice16 & 7))*32 + laneS)*4;   // +ch*1024 per chunk
    const int sdst    = slice16*132 + laneS*4;

    // ---- epilogue writer fragment index (t-invariant) ----
    const int mtE = bE >> 4, rbE = bE & 15;
    const int gE = rbE & 7, hi8E = rbE >> 3;
    const int sEidx = cc >> 3, tigE = cc & 3, halfE = (cc >> 2) & 1;
    const int idxE = ((tileM*2 + mtE)*64 + sEidx)*128 + (gE*4 + tigE)*4 + (hi8E + 2*halfE);

    float* outE = out + (size_t)gbE*T_*H_ + cc;
    const float* inpE = inp + (size_t)gbE*T_;

    float2 hoE = make_float2(0.f, 0.f);
    float2 zE;
    float kreg = 0.0f;
    unsigned bar = 0;

    #pragma unroll 1
    for (int t = 0; t < T_; t++){
        // ---- k finalize from step t-1 partials (leader column-tile) ----
        if (tileN == 0 && tid < 32){
            int gb = tileM*32 + tid;
            if (t == 0){
                kreg = 0.0f;
            } else {
                float s = kreg * wkH + bk0;
                #pragma unroll
                for (int n = 0; n < NTN; n++) s += __ldcg(&g_kpart[n*B_ + gb]);
                kreg = sigm(s);
            }
            g_k[gb] = kreg;
        }

        const float xbE = __ldg(inpE + t);

        // ================= phase 1: z, r =================
        float2 sz = make_float2(0.f, 0.f), sr = make_float2(0.f, 0.f);
        if (t > 0){
            float cz[2][4] = {{0,0,0,0},{0,0,0,0}};
            float cr[2][4] = {{0,0,0,0},{0,0,0,0}};
            float4 ph = __ldcg((const float4*)(g_hA_hi + base_f));
            float4 pl = __ldcg((const float4*)(g_hA_lo + base_f));
            #pragma unroll 1
            for (int ch = 0; ch < 8; ch++){
                float* ab = sm + OFF_RED + (ch & 1)*ABUF;
                *(float4*)(ab + sdst)         = ph;
                *(float4*)(ab + sdst + AHALF) = pl;
                __syncthreads();
                if (ch < 7){
                    ph = __ldcg((const float4*)(g_hA_hi + base_f + (ch+1)*1024));
                    pl = __ldcg((const float4*)(g_hA_lo + base_f + (ch+1)*1024));
                }
                #pragma unroll
                for (int j = 0; j < 2; j++){
                    const int sic = kq + 4*j;
                    const int sg  = ch*8 + sic;
                    float2 wz = *(const float2*)(sm + OFF_WZ + ((sg*4+ng)*32+lane)*2);
                    float2 wr = *(const float2*)(sm + OFF_WR + ((sg*4+ng)*32+lane)*2);
                    unsigned zh0=cvt_tf32(wz.x), zh1=cvt_tf32(wz.y);
                    unsigned zl0=cvt_tf32(wz.x-__uint_as_float(zh0));
                    unsigned zl1=cvt_tf32(wz.y-__uint_as_float(zh1));
                    unsigned rh0=cvt_tf32(wr.x), rh1=cvt_tf32(wr.y);
                    unsigned rl0=cvt_tf32(wr.x-__uint_as_float(rh0));
                    unsigned rl1=cvt_tf32(wr.y-__uint_as_float(rh1));
                    #pragma unroll
                    for (int mt = 0; mt < 2; mt++){
                        const float* ap = ab + (mt*8+sic)*132 + lane*4;
                        uint4 Ah = *(const uint4*)ap;
                        uint4 Al = *(const uint4*)(ap + AHALF);
                        mma_tf32(cz[mt], Ah, zh0, zh1);
                        mma_tf32(cz[mt], Ah, zl0, zl1);
                        mma_tf32(cz[mt], Al, zh0, zh1);
                        mma_tf32(cr[mt], Ah, rh0, rh1);
                        mma_tf32(cr[mt], Ah, rl0, rl1);
                        mma_tf32(cr[mt], Al, rh0, rh1);
                    }
                }
            }
            __syncthreads();   // staging region becomes reduction region
            #pragma unroll
            for (int mt = 0; mt < 2; mt++){
                int rw = mt*16 + g;
                *(float2*)(sm + OFF_RED + ((kq*16 + cpair)*33 + rw)*2)         = make_float2(cz[mt][0], cz[mt][1]);
                *(float2*)(sm + OFF_RED + ((kq*16 + cpair)*33 + rw + 8)*2)     = make_float2(cz[mt][2], cz[mt][3]);
                *(float2*)(sm + OFF_RED + (((4+kq)*16 + cpair)*33 + rw)*2)     = make_float2(cr[mt][0], cr[mt][1]);
                *(float2*)(sm + OFF_RED + (((4+kq)*16 + cpair)*33 + rw + 8)*2) = make_float2(cr[mt][2], cr[mt][3]);
            }
            __syncthreads();
            #pragma unroll
            for (int q = 0; q < 4; q++){
                float2 a = *(const float2*)(sm + OFF_RED + ((q*16 + cp)*33 + bE)*2);
                float2 b = *(const float2*)(sm + OFF_RED + (((4+q)*16 + cp)*33 + bE)*2);
                sz.x += a.x; sz.y += a.y; sr.x += b.x; sr.y += b.y;
            }
        }

        // per-thread epilogue: r first, write pre-split h*r fragments
        {
            const float2 vr0 = *(const float2*)(cs + 32 + jp2);
            const float2 brf = *(const float2*)(cs + 192 + jp2);
            float r0 = sigm(sr.x + xbE*vr0.x + brf.x);
            float r1 = sigm(sr.y + xbE*vr0.y + brf.y);
            float hr0 = hoE.x*r0, hr1 = hoE.y*r1;
            float h0h = tf32f(hr0), h1h = tf32f(hr1);
            g_hrA_hi[idxE]     = h0h;
            g_hrA_hi[idxE + 4] = h1h;
            g_hrA_lo[idxE]     = tf32f(hr0 - h0h);
            g_hrA_lo[idxE + 4] = tf32f(hr1 - h1h);
            const float2 vz0 = *(const float2*)(cs + jp2);
            const float2 bzf = *(const float2*)(cs + 160 + jp2);
            zE.x = sigm(sz.x + xbE*vz0.x + bzf.x);
            zE.y = sigm(sz.y + xbE*vz0.y + bzf.y);
        }

        bar++; group_barrier(cnt, bar*16);

        const float kvE = __ldcg(&g_k[gbE]);

        // ================= phase 2: h_tilde =================
        float2 sh = make_float2(0.f, 0.f);
        {
            float chh[2][4] = {{0,0,0,0},{0,0,0,0}};
            float4 ph = __ldcg((const float4*)(g_hrA_hi + base_f));
            float4 pl = __ldcg((const float4*)(g_hrA_lo + base_f));
            #pragma unroll 1
            for (int ch = 0; ch < 8; ch++){
                float* ab = sm + OFF_RED + (ch & 1)*ABUF;
                *(float4*)(ab + sdst)         = ph;
                *(float4*)(ab + sdst + AHALF) = pl;
                __syncthreads();
                if (ch < 7){
                    ph = __ldcg((const float4*)(g_hrA_hi + base_f + (ch+1)*1024));
                    pl = __ldcg((const float4*)(g_hrA_lo + base_f + (ch+1)*1024));
                }
                #pragma unroll
                for (int j = 0; j < 2; j++){
                    const int sic = kq + 4*j;
                    const int sg  = ch*8 + sic;
                    float2 wh = *(const float2*)(sm + OFF_WH + ((sg*4+ng)*32+lane)*2);
                    unsigned hh0=cvt_tf32(wh.x), hh1=cvt_tf32(wh.y);
                    unsigned hl0=cvt_tf32(wh.x-__uint_as_float(hh0));
                    unsigned hl1=cvt_tf32(wh.y-__uint_as_float(hh1));
                    #pragma unroll
                    for (int mt = 0; mt < 2; mt++){
                        const float* ap = ab + (mt*8+sic)*132 + lane*4;
                        uint4 Ah = *(const uint4*)ap;
                        uint4 Al = *(const uint4*)(ap + AHALF);
                        mma_tf32(chh[mt], Ah, hh0, hh1);
                        mma_tf32(chh[mt], Ah, hl0, hl1);
                        mma_tf32(chh[mt], Al, hh0, hh1);
                    }
                }
            }
            __syncthreads();
            #pragma unroll
            for (int mt = 0; mt < 2; mt++){
                int rw = mt*16 + g;
                *(float2*)(sm + OFF_RED + ((kq*16 + cpair)*33 + rw)*2)     = make_float2(chh[mt][0], chh[mt][1]);
                *(float2*)(sm + OFF_RED + ((kq*16 + cpair)*33 + rw + 8)*2) = make_float2(chh[mt][2], chh[mt][3]);
            }
            __syncthreads();
            #pragma unroll
            for (int q = 0; q < 4; q++){
                float2 a = *(const float2*)(sm + OFF_RED + ((q*16 + cp)*33 + bE)*2);
                sh.x += a.x; sh.y += a.y;
            }
        }

        // final per-thread epilogue: h update, write pre-split h fragments
        {
            const float2 vh0  = *(const float2*)(cs + 64 + jp2);
            const float2 v513 = *(const float2*)(cs + 96 + jp2);
            const float2 v514 = *(const float2*)(cs + 128 + jp2);
            const float2 bhf  = *(const float2*)(cs + 224 + jp2);
            float sk = stE * kvE;
            float a0 = sh.x + xbE*vh0.x + sk*v513.x + msE*v514.x + bhf.x;
            float a1 = sh.y + xbE*vh0.y + sk*v513.y + msE*v514.y + bhf.y;
            float t0 = tanh_(a0), t1 = tanh_(a1);
            float hn0 = (1.f - zE.x)*hoE.x + zE.x*t0;
            float hn1 = (1.f - zE.y)*hoE.y + zE.y*t1;
            __stcs((float2*)outE, make_float2(hn0, hn1));
            outE += H_;
            float h0h = tf32f(hn0), h1h = tf32f(hn1);
            g_hA_hi[idxE]     = h0h;
            g_hA_hi[idxE + 4] = h1h;
            g_hA_lo[idxE]     = tf32f(hn0 - h0h);
            g_hA_lo[idxE + 4] = tf32f(hn1 - h1h);
            hoE = make_float2(hn0, hn1);
            float kp = hn0*wkf.x + hn1*wkf.y;
            #pragma unroll
            for (int off = 8; off; off >>= 1)
                kp += __shfl_down_sync(0xffffffffu, kp, off, 16);
            if (cp == 0)
                g_kpart[tileN*B_ + gbE] = kp;
        }

        bar++; group_barrier(cnt, bar*16);
    }
}

extern "C" void kernel_launch(void* const* d_in, const int* in_sizes, int n_in,
                              void* d_out, int out_size) {
    (void)in_sizes; (void)n_in; (void)out_size;
    const float* inputs = (const float*)d_in[0];
    const float* St     = (const float*)d_in[1];
    const float* Mass   = (const float*)d_in[2];
    const float* Wz     = (const float*)d_in[3];
    const float* bz     = (const float*)d_in[4];
    const float* Wr     = (const float*)d_in[5];
    const float* br     = (const float*)d_in[6];
    const float* Wh     = (const float*)d_in[7];
    const float* bh     = (const float*)d_in[8];
    const float* Wk     = (const float*)d_in[9];
    const float* bk     = (const float*)d_in[10];
    float* out = (float*)d_out;

    cudaFuncSetAttribute(mcgru_kernel, cudaFuncAttributeMaxDynamicSharedMemorySize, SMEM_BYTES);

    init_kernel<<<1, 256>>>();
    mcgru_kernel<<<NCTA, NTHR, SMEM_BYTES>>>(inputs, St, Mass, Wz, bz, Wr, br,
                                             Wh, bh, Wk, bk, out);
}

// round 17
// speedup vs baseline: 2.1842x; 1.1750x over previous
#include <cuda_runtime.h>
#include <cuda_bf16.h>

#define B_   256
#define T_   1000
#define H_   512
#define NTN  16
#define NTM  8
#define NCTA 128
#define NTHR 512

// uint (4B) offsets in dynamic smem
// Weights pre-split to bf16 hi/lo, packed bf16x2, B-fragment order:
//   uint[(s*4+ng)*64 + lane*2 + breg]; s=k16-step (0..31), ng=n-block (0..3)
#define U_WZH 0
#define U_WZL 8192
#define U_WRH 16384
#define U_WRL 24576
#define U_WHH 32768
#define U_WHL 40960
#define U_RED 49152              // 8448-float region: staging (2 x 2048 uints) + reduction alias
#define U_CS  57600              // 256 floats
#define SMEM_FLOATS 57856
#define SMEM_BYTES  (SMEM_FLOATS*4)   // 231424 B

#define ABUFU  2048              // staging buffer (hi 1024 + lo 1024 uints)
#define AHALFU 1024

// persistent device state: h / h*r pre-split to bf16 hi/lo, packed bf16x2 (cols cc,cc+1),
// A-fragment order: uint idx = ((B2*32+s)*32 + (g*4+t))*4 + r
//   B2=(b>>4), m16=b&15, g=m16&7, s=k>>4, kl=k&15, t=(kl>>1)&3, r=(m16>>3)+2*(kl>>3)
__device__ unsigned g_hA_hi[B_*H_/2];
__device__ unsigned g_hA_lo[B_*H_/2];
__device__ unsigned g_hrA_hi[B_*H_/2];
__device__ unsigned g_hrA_lo[B_*H_/2];
__device__ float g_k[B_];
__device__ float g_kpart[NTN*B_];
__device__ unsigned g_cnt[NTM*32];

__device__ __forceinline__ void split_bf16(float w0, float w1, unsigned& hi, unsigned& lo){
    __nv_bfloat16 h0 = __float2bfloat16_rn(w0), h1 = __float2bfloat16_rn(w1);
    float f0 = __bfloat162float(h0), f1 = __bfloat162float(h1);
    __nv_bfloat16 l0 = __float2bfloat16_rn(w0 - f0), l1 = __float2bfloat16_rn(w1 - f1);
    hi = ((unsigned)__bfloat16_as_ushort(h1) << 16) | (unsigned)__bfloat16_as_ushort(h0);
    lo = ((unsigned)__bfloat16_as_ushort(l1) << 16) | (unsigned)__bfloat16_as_ushort(l0);
}
__device__ __forceinline__ void mma_bf16(float c[4], uint4 a, uint2 b){
    asm volatile("mma.sync.aligned.m16n8k16.row.col.f32.bf16.bf16.f32 "
                 "{%0,%1,%2,%3}, {%4,%5,%6,%7}, {%8,%9}, {%0,%1,%2,%3};"
                 : "+f"(c[0]), "+f"(c[1]), "+f"(c[2]), "+f"(c[3])
                 : "r"(a.x), "r"(a.y), "r"(a.z), "r"(a.w), "r"(b.x), "r"(b.y));
}
__device__ __forceinline__ float sigm(float x){ return 1.0f/(1.0f+__expf(-x)); }
__device__ __forceinline__ float tanh_(float x){ return 2.0f/(1.0f+__expf(-2.0f*x)) - 1.0f; }

__device__ __forceinline__ void group_barrier(unsigned* cnt, unsigned target){
    __syncthreads();
    if (threadIdx.x == 0){
        asm volatile("red.release.gpu.global.add.u32 [%0], 1;" :: "l"(cnt) : "memory");
        unsigned v;
        do { asm volatile("ld.acquire.gpu.global.u32 %0, [%1];" : "=r"(v) : "l"(cnt) : "memory"); } while (v < target);
    }
    __syncthreads();
}

__global__ void init_kernel(){
    int i = threadIdx.x;
    if (i < NTM*32) g_cnt[i] = 0u;
}

__global__ void __launch_bounds__(NTHR, 1) mcgru_kernel(
    const float* __restrict__ inp, const float* __restrict__ St, const float* __restrict__ Mass,
    const float* __restrict__ Wz, const float* __restrict__ bz,
    const float* __restrict__ Wr, const float* __restrict__ br,
    const float* __restrict__ Wh, const float* __restrict__ bh,
    const float* __restrict__ Wk, const float* __restrict__ bk,
    float* __restrict__ out)
{
    extern __shared__ unsigned smu[];
    float* red = (float*)(smu + U_RED);
    float* cs  = (float*)(smu + U_CS);

    const int tid   = threadIdx.x;
    const int lane  = tid & 31;
    const int wid   = tid >> 5;
    const int g     = lane >> 2;       // mma group id
    const int tig   = lane & 3;        // thread-in-group
    const int kq    = wid & 3;         // strided k-quarter (s mod 4)
    const int ng    = wid >> 2;        // n-block (8 cols)
    const int cpair = 4*ng + tig;
    const int tileN = blockIdx.x & (NTN-1);
    const int tileM = blockIdx.x >> 4;
    const int c0    = tileN * 32;
    unsigned* cnt   = &g_cnt[tileM*32];

    // epilogue ownership: batch bE, cols cc..cc+1
    const int bE  = tid >> 4;
    const int cp  = tid & 15;
    const int jp2 = 2*cp;
    const int cc  = c0 + jp2;
    const int gbE = tileM*32 + bE;

    // ---- prologue: pre-split weights to bf16 hi/lo in B-fragment order ----
    for (int i = tid; i < 8192; i += NTHR){
        int sgblk = i >> 6;            // s*4 + ng
        int ln    = (i >> 1) & 31;
        int brg   = i & 1;
        int gg = ln >> 2, tg = ln & 3;
        int col  = c0 + 8*(sgblk & 3) + gg;
        int krow = 16*(sgblk >> 2) + 2*tg + 8*brg;
        int r0 = (1 + krow)*H_ + col;
        int r1 = r0 + H_;
        unsigned hi, lo;
        split_bf16(Wz[r0], Wz[r1], hi, lo); smu[U_WZH + i] = hi; smu[U_WZL + i] = lo;
        split_bf16(Wr[r0], Wr[r1], hi, lo); smu[U_WRH + i] = hi; smu[U_WRL + i] = lo;
        split_bf16(Wh[r0], Wh[r1], hi, lo); smu[U_WHH + i] = hi; smu[U_WHL + i] = lo;
    }
    if (tid < 32){
        cs[tid]       = Wz[c0 + tid];
        cs[32 + tid]  = Wr[c0 + tid];
        cs[64 + tid]  = Wh[c0 + tid];
        cs[96 + tid]  = Wh[513*H_ + c0 + tid];
        cs[128 + tid] = Wh[514*H_ + c0 + tid];
        cs[160 + tid] = bz[c0 + tid];
        cs[192 + tid] = br[c0 + tid];
        cs[224 + tid] = bh[c0 + tid];
    }
    const float wkH = __ldg(&Wk[H_]);
    const float bk0 = __ldg(&bk[0]);
    const float2 wkf = *(const float2*)&Wk[cc];
    const float stE = __ldg(&St[gbE]);
    const float msE = __ldg(&Mass[gbE]);
    __syncthreads();

    // ---- staging copy constants (pure uint2 copy) ----
    const int biS = tid >> 6;                   // block 0..7 = mtb*4 + sl
    const int wS  = tid & 63;
    const int mtbS = biS >> 2, slS = biS & 3;
    const int abase = ((tileM*2 + mtbS)*32 + slS)*64 + wS;   // uint2 units
    const int cpy   = biS*64 + wS;                           // uint2 units in buffer
    const uint2* s1h = ((const uint2*)g_hA_hi)  + abase;
    const uint2* s1l = ((const uint2*)g_hA_lo)  + abase;
    const uint2* s2h = ((const uint2*)g_hrA_hi) + abase;
    const uint2* s2l = ((const uint2*)g_hrA_lo) + abase;

    // ---- epilogue writer fragment index ----
    const int m16E = bE & 15;
    const int gE = m16E & 7;
    const int sE = cc >> 4, klE = cc & 15;
    const int tE = (klE >> 1) & 3;
    const int rE = (m16E >> 3) + 2*(klE >> 3);
    const int idxE = (((tileM*2 + (bE>>4))*32 + sE)*32 + (gE*4 + tE))*4 + rE;

    float* outE = out + (size_t)gbE*T_*H_ + cc;
    const float* inpE = inp + (size_t)gbE*T_;

    float2 hoE = make_float2(0.f, 0.f);
    float2 zE;
    float kreg = 0.0f;
    unsigned bar = 0;

    #pragma unroll 1
    for (int t = 0; t < T_; t++){
        // ---- k finalize from step t-1 partials (leader column-tile) ----
        if (tileN == 0 && tid < 32){
            int gb = tileM*32 + tid;
            if (t == 0){
                kreg = 0.0f;
            } else {
                float s = kreg * wkH + bk0;
                #pragma unroll
                for (int n = 0; n < NTN; n++) s += __ldcg(&g_kpart[n*B_ + gb]);
                kreg = sigm(s);
            }
            g_k[gb] = kreg;
        }

        const float xbE = __ldg(inpE + t);

        // ================= phase 1: z, r =================
        float2 sz = make_float2(0.f, 0.f), sr = make_float2(0.f, 0.f);
        if (t > 0){
            float cz[2][4] = {{0,0,0,0},{0,0,0,0}};
            float cr[2][4] = {{0,0,0,0},{0,0,0,0}};
            uint2 ph = __ldcg(s1h), pl = __ldcg(s1l);
            #pragma unroll 1
            for (int ch = 0; ch < 8; ch++){
                unsigned* ab = smu + U_RED + (ch & 1)*ABUFU;
                ((uint2*)ab)[cpy]            = ph;
                ((uint2*)(ab + AHALFU))[cpy] = pl;
                __syncthreads();
                if (ch < 7){
                    ph = __ldcg(s1h + (ch+1)*256);
                    pl = __ldcg(s1l + (ch+1)*256);
                }
                const int sgblk = (ch*4 + kq)*4 + ng;
                uint2 bzh = *(const uint2*)(smu + U_WZH + sgblk*64 + lane*2);
                uint2 bzl = *(const uint2*)(smu + U_WZL + sgblk*64 + lane*2);
                uint2 brh = *(const uint2*)(smu + U_WRH + sgblk*64 + lane*2);
                uint2 brl = *(const uint2*)(smu + U_WRL + sgblk*64 + lane*2);
                const unsigned* ap0 = ab + (0*4 + kq)*128 + lane*4;
                const unsigned* ap1 = ab + (1*4 + kq)*128 + lane*4;
                uint4 Ah0 = *(const uint4*)ap0;
                uint4 Al0 = *(const uint4*)(ap0 + AHALFU);
                uint4 Ah1 = *(const uint4*)ap1;
                uint4 Al1 = *(const uint4*)(ap1 + AHALFU);
                mma_bf16(cz[0], Ah0, bzh); mma_bf16(cz[0], Ah0, bzl); mma_bf16(cz[0], Al0, bzh);
                mma_bf16(cz[1], Ah1, bzh); mma_bf16(cz[1], Ah1, bzl); mma_bf16(cz[1], Al1, bzh);
                mma_bf16(cr[0], Ah0, brh); mma_bf16(cr[0], Ah0, brl); mma_bf16(cr[0], Al0, brh);
                mma_bf16(cr[1], Ah1, brh); mma_bf16(cr[1], Ah1, brl); mma_bf16(cr[1], Al1, brh);
            }
            __syncthreads();   // staging region becomes reduction region
            #pragma unroll
            for (int mt = 0; mt < 2; mt++){
                int rw = mt*16 + g;
                *(float2*)(red + ((kq*16 + cpair)*33 + rw)*2)         = make_float2(cz[mt][0], cz[mt][1]);
                *(float2*)(red + ((kq*16 + cpair)*33 + rw + 8)*2)     = make_float2(cz[mt][2], cz[mt][3]);
                *(float2*)(red + (((4+kq)*16 + cpair)*33 + rw)*2)     = make_float2(cr[mt][0], cr[mt][1]);
                *(float2*)(red + (((4+kq)*16 + cpair)*33 + rw + 8)*2) = make_float2(cr[mt][2], cr[mt][3]);
            }
            __syncthreads();
            #pragma unroll
            for (int q = 0; q < 4; q++){
                float2 a = *(const float2*)(red + ((q*16 + cp)*33 + bE)*2);
                float2 b = *(const float2*)(red + (((4+q)*16 + cp)*33 + bE)*2);
                sz.x += a.x; sz.y += a.y; sr.x += b.x; sr.y += b.y;
            }
        }

        // per-thread epilogue: r first, write pre-split h*r fragments
        {
            const float2 vr0 = *(const float2*)(cs + 32 + jp2);
            const float2 brf = *(const float2*)(cs + 192 + jp2);
            float r0 = sigm(sr.x + xbE*vr0.x + brf.x);
            float r1 = sigm(sr.y + xbE*vr0.y + brf.y);
            float hr0 = hoE.x*r0, hr1 = hoE.y*r1;
            unsigned hi, lo;
            split_bf16(hr0, hr1, hi, lo);
            g_hrA_hi[idxE] = hi;
            g_hrA_lo[idxE] = lo;
            const float2 vz0 = *(const float2*)(cs + jp2);
            const float2 bzf = *(const float2*)(cs + 160 + jp2);
            zE.x = sigm(sz.x + xbE*vz0.x + bzf.x);
            zE.y = sigm(sz.y + xbE*vz0.y + bzf.y);
        }

        bar++; group_barrier(cnt, bar*16);

        const float kvE = __ldcg(&g_k[gbE]);

        // ================= phase 2: h_tilde =================
        float2 sh = make_float2(0.f, 0.f);
        {
            float chh[2][4] = {{0,0,0,0},{0,0,0,0}};
            uint2 ph = __ldcg(s2h), pl = __ldcg(s2l);
            #pragma unroll 1
            for (int ch = 0; ch < 8; ch++){
                unsigned* ab = smu + U_RED + (ch & 1)*ABUFU;
                ((uint2*)ab)[cpy]            = ph;
                ((uint2*)(ab + AHALFU))[cpy] = pl;
                __syncthreads();
                if (ch < 7){
                    ph = __ldcg(s2h + (ch+1)*256);
                    pl = __ldcg(s2l + (ch+1)*256);
                }
                const int sgblk = (ch*4 + kq)*4 + ng;
                uint2 bhh = *(const uint2*)(smu + U_WHH + sgblk*64 + lane*2);
                uint2 bhl = *(const uint2*)(smu + U_WHL + sgblk*64 + lane*2);
                const unsigned* ap0 = ab + (0*4 + kq)*128 + lane*4;
                const unsigned* ap1 = ab + (1*4 + kq)*128 + lane*4;
                uint4 Ah0 = *(const uint4*)ap0;
                uint4 Al0 = *(const uint4*)(ap0 + AHALFU);
                uint4 Ah1 = *(const uint4*)ap1;
                uint4 Al1 = *(const uint4*)(ap1 + AHALFU);
                mma_bf16(chh[0], Ah0, bhh); mma_bf16(chh[0], Ah0, bhl); mma_bf16(chh[0], Al0, bhh);
                mma_bf16(chh[1], Ah1, bhh); mma_bf16(chh[1], Ah1, bhl); mma_bf16(chh[1], Al1, bhh);
            }
            __syncthreads();
            #pragma unroll
            for (int mt = 0; mt < 2; mt++){
                int rw = mt*16 + g;
                *(float2*)(red + ((kq*16 + cpair)*33 + rw)*2)     = make_float2(chh[mt][0], chh[mt][1]);
                *(float2*)(red + ((kq*16 + cpair)*33 + rw + 8)*2) = make_float2(chh[mt][2], chh[mt][3]);
            }
            __syncthreads();
            #pragma unroll
            for (int q = 0; q < 4; q++){
                float2 a = *(const float2*)(red + ((q*16 + cp)*33 + bE)*2);
                sh.x += a.x; sh.y += a.y;
            }
        }

        // final per-thread epilogue: h update, write pre-split h fragments
        {
            const float2 vh0  = *(const float2*)(cs + 64 + jp2);
            const float2 v513 = *(const float2*)(cs + 96 + jp2);
            const float2 v514 = *(const float2*)(cs + 128 + jp2);
            const float2 bhf  = *(const float2*)(cs + 224 + jp2);
            float sk = stE * kvE;
            float a0 = sh.x + xbE*vh0.x + sk*v513.x + msE*v514.x + bhf.x;
            float a1 = sh.y + xbE*vh0.y + sk*v513.y + msE*v514.y + bhf.y;
            float t0 = tanh_(a0), t1 = tanh_(a1);
            float hn0 = (1.f - zE.x)*hoE.x + zE.x*t0;
            float hn1 = (1.f - zE.y)*hoE.y + zE.y*t1;
            __stcs((float2*)outE, make_float2(hn0, hn1));
            outE += H_;
            unsigned hi, lo;
            split_bf16(hn0, hn1, hi, lo);
            g_hA_hi[idxE] = hi;
            g_hA_lo[idxE] = lo;
            hoE = make_float2(hn0, hn1);
            float kp = hn0*wkf.x + hn1*wkf.y;
            #pragma unroll
            for (int off = 8; off; off >>= 1)
                kp += __shfl_down_sync(0xffffffffu, kp, off, 16);
            if (cp == 0)
                g_kpart[tileN*B_ + gbE] = kp;
        }

        bar++; group_barrier(cnt, bar*16);
    }
}

extern "C" void kernel_launch(void* const* d_in, const int* in_sizes, int n_in,
                              void* d_out, int out_size) {
    (void)in_sizes; (void)n_in; (void)out_size;
    const float* inputs = (const float*)d_in[0];
    const float* St     = (const float*)d_in[1];
    const float* Mass   = (const float*)d_in[2];
    const float* Wz     = (const float*)d_in[3];
    const float* bz     = (const float*)d_in[4];
    const float* Wr     = (const float*)d_in[5];
    const float* br     = (const float*)d_in[6];
    const float* Wh     = (const float*)d_in[7];
    const float* bh     = (const float*)d_in[8];
    const float* Wk     = (const float*)d_in[9];
    const float* bk     = (const float*)d_in[10];
    float* out = (float*)d_out;

    cudaFuncSetAttribute(mcgru_kernel, cudaFuncAttributeMaxDynamicSharedMemorySize, SMEM_BYTES);

    init_kernel<<<1, 256>>>();
    mcgru_kernel<<<NCTA, NTHR, SMEM_BYTES>>>(inputs, St, Mass, Wz, bz, Wr, br,
                                             Wh, bh, Wk, bk, out);
}